// round 15
// baseline (speedup 1.0000x reference)
#include <cuda_runtime.h>

#define EPSF 1e-8f
#define LNK   16
#define DST   255
#define TUN   1020
#define NCH   8
#define PAIRS 28          // row pairs per block
#define ROWS  56
#define SSTR  58          // words per group slot
#define PLW   (32*SSTR)   // 1856 words per plane
#define BUFDW (4*PLW)     // 7424 data words per buffer
#define BUFW  (BUFDW+64)  // + zero region
#define BUFB  (BUFW*4)    // 29952 bytes
#define ZBYTE (BUFDW*4)   // 29696, fits u16
#define SCHW  176         // pad-to-4 per bin
#define THR   1024

// smem word map
#define W_SCHED (2*BUFW)                  // 14976
#define W_OFF   (W_SCHED + (NCH*SCHW)/2)  // +704
#define W_CUR   (W_OFF + NCH*17)
#define W_NL    (W_CUR + NCH*17)          // [2][56*17]
#define W_INV   (W_NL + 2*ROWS*17)
#define W_LOSS  (W_INV + 16)
#define W_FIN   (W_LOSS + 32)
#define W_LAST  (W_FIN + 32)
#define W_TOTAL (W_LAST + 1)

__device__ float    g_partials[512];
__device__ unsigned g_count;

__device__ __forceinline__ unsigned long long lds64(unsigned a) {
    unsigned long long v;
    asm volatile("ld.shared.b64 %0, [%1];" : "=l"(v) : "r"(a));
    return v;
}
__device__ __forceinline__ unsigned long long addx2(unsigned long long a,
                                                    unsigned long long b) {
    unsigned long long r;
    asm("add.rn.f32x2 %0, %1, %2;" : "=l"(r) : "l"(a), "l"(b));
    return r;
}

__global__ __launch_bounds__(THR, 2) void loss_kernel(
    const float* __restrict__ pred,   // [B,1020]
    const float* __restrict__ dem,    // [B,255]
    const float* __restrict__ clu,    // [B,16]
    const float* __restrict__ caps,   // [16]
    const int*   __restrict__ t2l,    // [1020]
    float* __restrict__ out,
    int B, int nb, float invB)
{
    extern __shared__ float smf[];
    unsigned short* s_sched = (unsigned short*)(smf + W_SCHED);
    int*   s_off  = (int*)(smf + W_OFF);
    int*   s_cur  = (int*)(smf + W_CUR);
    float* s_nl   = smf + W_NL;
    float* s_inv  = smf + W_INV;
    float* s_loss = smf + W_LOSS;
    float* s_fin  = smf + W_FIN;
    int*   s_last = (int*)(smf + W_LAST);

    const int tid  = threadIdx.x;
    const int warp = tid >> 5;          // 0..31
    const int lane = tid & 31;
    const int base = blockIdx.x * ROWS;
    const unsigned sm32 = (unsigned)__cvta_generic_to_shared(smf);
    const int bin = warp & 15;
    const int gh  = warp >> 4;

    // each staging warp owns ONE pair: rows base+warp, base+warp+28
    float4 ra, rb; float da, db;
    unsigned long long acc0 = 0ull, acc1 = 0ull;

    #define LOADU(ch)                                                             \
    if (warp < PAIRS) {                                                           \
        const int gg = (ch) * 32 + lane;                                          \
        const int r0 = base + warp, r1 = r0 + PAIRS;                              \
        const bool ok = (gg < DST);                                               \
        const bool o0 = ok && (r0 < B), o1 = ok && (r1 < B);                      \
        ra = o0 ? ((const float4*)pred)[(size_t)r0 * DST + gg]                    \
                : make_float4(0,0,0,0);                                           \
        rb = o1 ? ((const float4*)pred)[(size_t)r1 * DST + gg]                    \
                : make_float4(0,0,0,0);                                           \
        da = o0 ? dem[(size_t)r0 * DST + gg] : 0.0f;                              \
        db = o1 ? dem[(size_t)r1 * DST + gg] : 0.0f;                              \
    }

    #define STSU(buf)                                                             \
    if (warp < PAIRS) {                                                           \
        float* bp = smf + (buf) * BUFW;                                           \
        const int wb = lane * SSTR + warp * 2;                                    \
        ((float2*)bp)[(0 * PLW + wb) >> 1] = make_float2(ra.x * da, rb.x * db);   \
        ((float2*)bp)[(1 * PLW + wb) >> 1] = make_float2(ra.y * da, rb.y * db);   \
        ((float2*)bp)[(2 * PLW + wb) >> 1] = make_float2(ra.z * da, rb.z * db);   \
        ((float2*)bp)[(3 * PLW + wb) >> 1] = make_float2(ra.w * da, rb.w * db);   \
    }

    // two warps per bin: gh selects half of the (pad-to-4) entry list
    #define GATHER(c)                                                             \
    {                                                                             \
        const unsigned lbase = sm32 + (unsigned)(((c) & 1) * BUFB)                \
                             + (unsigned)(lane << 3);                             \
        const unsigned short* sc = s_sched + (c) * SCHW;                          \
        const int lo = s_off[(c) * 17 + bin];                                     \
        const int half = (s_off[(c) * 17 + bin + 1] - lo) >> 1;  /* even */       \
        int k = lo + (gh ? half : 0);                                             \
        const int ke = k + half;                                                  \
        _Pragma("unroll 2")                                                       \
        for (; k < ke; k += 2) {                                                  \
            const unsigned o0 = sc[k];                                            \
            const unsigned o1 = sc[k + 1];                                        \
            acc0 = addx2(acc0, lds64(lbase + o0));                                \
            acc1 = addx2(acc1, lds64(lbase + o1));                                \
        }                                                                         \
    }

    #define ITER(c)                                                               \
    {                                                                             \
        if ((c) + 1 < NCH) LOADU((c) + 1);                                        \
        GATHER(c);                                                                \
        if ((c) + 1 < NCH) STSU(((c) + 1) & 1);                                   \
        __syncthreads();                                                          \
    }

    // ---------------- prologue ----------------------------------------------
    LOADU(0);

    // schedule build: warp c (<8) sorts chunk c by bin (pad-to-4)
    if (warp < 8) {
        const int c = warp;
        int* cur = s_cur + c * 17;
        int* off = s_off + c * 17;
        if (lane < 17) cur[lane] = 0;
        int bins[4];
        #pragma unroll
        for (int q = 0; q < 4; ++q) {
            const int t = c * 128 + q * 32 + lane;
            bins[q] = (t < TUN) ? t2l[t] : 16;
        }
        __syncwarp();
        #pragma unroll
        for (int q = 0; q < 4; ++q) {
            const unsigned peers = __match_any_sync(0xffffffffu, bins[q]);
            const int rank = __popc(peers & ((1u << lane) - 1u));
            if (rank == 0) cur[bins[q]] += __popc(peers);
            __syncwarp();
        }
        if (lane < 17) {                           // pad-to-4 exclusive scan
            int o = 0;
            for (int i = 0; i < lane; ++i) o += (cur[i] + 3) & ~3;
            off[lane] = o;
        }
        __syncwarp();
        for (int i = lane; i < SCHW; i += 32)
            s_sched[c * SCHW + i] = (unsigned short)ZBYTE;
        if (lane < 17) cur[lane] = off[lane];
        __syncwarp();
        #pragma unroll
        for (int q = 0; q < 4; ++q) {
            const unsigned peers = __match_any_sync(0xffffffffu, bins[q]);
            const int rank = __popc(peers & ((1u << lane) - 1u));
            const int bse  = cur[bins[q]];
            __syncwarp();
            if (rank == 0) cur[bins[q]] = bse + __popc(peers);
            __syncwarp();
            if (bins[q] < 16) {
                const int tl = q * 32 + lane;
                const unsigned o = (unsigned)(tl & 3) * (PLW * 4)
                                 + (unsigned)(tl >> 2) * (SSTR * 4);
                s_sched[c * SCHW + bse + rank] = (unsigned short)o;
            }
        }
    }
    // zero regions of both buffers (warps 16-19)
    if (tid >= 512 && tid < 640) {
        const int i = tid - 512;
        smf[(i >> 6) * BUFW + BUFDW + (i & 63)] = 0.0f;
    }
    if (tid < LNK) s_inv[tid] = 1.0f / (caps[tid] + EPSF);

    STSU(0);                       // chunk 0 -> buffer 0
    __syncthreads();

    // ---------------- fully unrolled pipeline --------------------------------
    ITER(0); ITER(1); ITER(2); ITER(3);
    ITER(4); ITER(5); ITER(6); ITER(7);

    // ---------------- stats ---------------------------------------------------
    {
        const unsigned long long t = addx2(acc0, acc1);
        const float lo = __uint_as_float((unsigned)(t & 0xffffffffull));
        const float hi = __uint_as_float((unsigned)(t >> 32));
        float* nlh = smf + W_NL + gh * (ROWS * 17);
        if (lane < PAIRS) {
            nlh[lane * 17 + bin] = lo;                 // row = lane
            nlh[(lane + PAIRS) * 17 + bin] = hi;       // row = lane + 28
        }
    }
    __syncthreads();

    float lsum = 0.0f;
    {
        const int rid = (warp << 1) + (lane >> 4);     // 0..63
        const int j = lane & 15;
        const int brow = base + rid;
        const bool rok = (rid < ROWS) && (brow < B);
        const float traf = rok ? (smf[W_NL + rid * 17 + j]
                                + smf[W_NL + ROWS * 17 + rid * 17 + j]) : 0.0f;
        const float u   = traf * s_inv[j];
        const float cur = rok ? clu[(size_t)brow * LNK + j] : 0.0f;

        float smn = u;
        #pragma unroll
        for (int off = 1; off < 16; off <<= 1)
            smn += __shfl_xor_sync(0xffffffffu, smn, off);
        const float mean = smn * (1.0f / 16.0f);

        const float dv = u - mean;
        float q2  = dv * dv;
        float dot = u * cur;
        float mx  = u;
        #pragma unroll
        for (int off = 1; off < 16; off <<= 1) {
            q2  += __shfl_xor_sync(0xffffffffu, q2, off);
            dot += __shfl_xor_sync(0xffffffffu, dot, off);
            mx   = fmaxf(mx, __shfl_xor_sync(0xffffffffu, mx, off));
        }
        if (j == 0 && rok)
            lsum = 0.3f * (q2 * (1.0f / 15.0f)) + 0.5f * dot + 0.2f * mx;
    }
    lsum += __shfl_xor_sync(0xffffffffu, lsum, 16);
    if (lane == 0) s_loss[warp] = lsum;
    __syncthreads();

    // ---------------- deterministic single-launch reduction -------------------
    if (tid == 0) {
        float t = 0.0f;
        #pragma unroll
        for (int w = 0; w < 32; ++w) t += s_loss[w];
        g_partials[blockIdx.x] = t;
        __threadfence();
        const unsigned old = atomicAdd(&g_count, 1u);
        *s_last = (old == (unsigned)(nb - 1));
    }
    __syncthreads();

    if (*s_last) {
        float v = (tid < nb) ? __ldcg(&g_partials[tid]) : 0.0f;
        #pragma unroll
        for (int off = 16; off; off >>= 1)
            v += __shfl_xor_sync(0xffffffffu, v, off);
        if (lane == 0) s_fin[warp] = v;
        __syncthreads();
        if (warp == 0) {
            float t = s_fin[lane];
            #pragma unroll
            for (int off = 16; off; off >>= 1)
                t += __shfl_xor_sync(0xffffffffu, t, off);
            if (lane == 0) {
                out[0] = t * invB;
                g_count = 0;
            }
        }
    }
}

extern "C" void kernel_launch(void* const* d_in, const int* in_sizes, int n_in,
                              void* d_out, int out_size)
{
    const float* pred = (const float*)d_in[0];
    const float* dem  = (const float*)d_in[1];
    const float* clu  = (const float*)d_in[2];
    const float* caps = (const float*)d_in[3];
    const int*   t2l  = (const int*)d_in[4];
    float* out = (float*)d_out;

    const int B  = in_sizes[0] / TUN;           // 16384
    int nb = (B + ROWS - 1) / ROWS;             // 293
    if (nb > 512) nb = 512;

    const int smem_bytes = W_TOTAL * 4;         // ~71.8 KB
    cudaFuncSetAttribute(loss_kernel,
                         cudaFuncAttributeMaxDynamicSharedMemorySize, smem_bytes);
    loss_kernel<<<nb, THR, smem_bytes>>>(pred, dem, clu, caps, t2l, out,
                                         B, nb, 1.0f / (float)B);
}